// round 17
// baseline (speedup 1.0000x reference)
#include <cuda_runtime.h>
#include <cuda_bf16.h>
#include <cstdint>

#define NN 50000
#define NE 800000
#define F  128
#define NG 100
#define SCAN_B 1024
#define NSB ((NN + SCAN_B - 1) / SCAN_B)   // 49
#define NCHUNK 3

// ---- scratch (static __device__ globals; no allocation anywhere) ----
__device__ __align__(16) float g_deg[NN];
__device__ __align__(16) float g_dinv[NN];
__device__ __align__(16) uint32_t g_hb[NN * 64];    // layer-1 XW, bf16x2
__device__ __align__(16) uint32_t g_hb2[NN * 64];   // layer-2 XW, bf16x2 (no WAR with gather1)
__device__ __align__(16) uint32_t g_actb[NN * 64];  // relu activations, bf16x2
__device__ __align__(16) float g_pool[NG * F];
__device__ __align__(16) float g_cnt[NG];
__device__ int   g_cnt_in[NN];
__device__ int   g_incl[NN];
__device__ int   g_bsum[NSB];
__device__ int   g_ptr[NN + 1];
__device__ int   g_cur[NN];
__device__ __align__(16) int   g_csr_row[NE];
__device__ __align__(16) float g_csr_norm[NE];

// packed f32x2 helpers (B300 FFMA2 — only reachable via PTX)
#define FMA2(d, a, b) \
    asm("fma.rn.f32x2 %0, %1, %2, %0;" : "+l"(d) : "l"(a), "l"(b))
#define PACK2(out, lo, hi) \
    asm("mov.b64 %0, {%1, %2};" : "=l"(out) : "f"(lo), "f"(hi))
#define UNPACK2(lo, hi, in) \
    asm("mov.b64 {%0, %1}, %2;" : "=f"(lo), "=f"(hi) : "l"(in))
// d = bf16x2 with lo=a, hi=b
#define CVT_BF2(d, a, b) \
    asm("cvt.rn.bf16x2.f32 %0, %1, %2;" : "=r"(d) : "f"(b), "f"(a))

__device__ __forceinline__ float2 bf2f(uint32_t u) {
    return __bfloat1622float2(*reinterpret_cast<__nv_bfloat162*>(&u));
}

// ================= CSR build =================
__global__ void zero_misc_kernel() {
    int i = blockIdx.x * blockDim.x + threadIdx.x;
    if (i < NN) { g_deg[i] = 0.f; g_cnt_in[i] = 0; }
    if (i < NG * F) g_pool[i] = 0.f;
    if (i < NG) g_cnt[i] = 0.f;
}

__global__ void deg_count_kernel(const int* __restrict__ ei,
                                 const float* __restrict__ ew) {
    int t = blockIdx.x * blockDim.x + threadIdx.x;
    int e = t * 4;
    if (e < NE) {
        int4   c4 = *reinterpret_cast<const int4*>(&ei[NE + e]);
        float4 w4 = *reinterpret_cast<const float4*>(&ew[e]);
        atomicAdd(&g_deg[c4.x], w4.x);
        atomicAdd(&g_cnt_in[c4.x], 1);
        atomicAdd(&g_deg[c4.y], w4.y);
        atomicAdd(&g_cnt_in[c4.y], 1);
        atomicAdd(&g_deg[c4.z], w4.z);
        atomicAdd(&g_cnt_in[c4.z], 1);
        atomicAdd(&g_deg[c4.w], w4.w);
        atomicAdd(&g_cnt_in[c4.w], 1);
    }
}

// per-block inclusive scan of counts + fused dinv / graph-count work
__global__ void scan1_kernel(const int* __restrict__ batch) {
    __shared__ int s[SCAN_B];
    int tid = threadIdx.x;
    int i = blockIdx.x * SCAN_B + tid;
    int v = (i < NN) ? g_cnt_in[i] : 0;
    if (i < NN) {
        g_dinv[i] = rsqrtf(g_deg[i] + 1.0f);
        int g = batch[i];
        if (g < 0) g = 0;
        if (g >= NG) g = NG - 1;
        atomicAdd(&g_cnt[g], 1.0f);
    }
    s[tid] = v;
    __syncthreads();
#pragma unroll
    for (int off = 1; off < SCAN_B; off <<= 1) {
        int t = (tid >= off) ? s[tid - off] : 0;
        __syncthreads();
        s[tid] += t;
        __syncthreads();
    }
    if (i < NN) g_incl[i] = s[tid];
    if (tid == SCAN_B - 1) g_bsum[blockIdx.x] = s[tid];
}

// combine: each CTA locally scans the 49 block sums (smem), then finalizes ptr/cur
__global__ void scan3_kernel() {
    __shared__ int spre[NSB];
    int t = threadIdx.x;
    if (t < NSB) spre[t] = g_bsum[t];
    __syncthreads();
    if (t == 0) {
        int run = 0;
#pragma unroll 7
        for (int b = 0; b < NSB; b++) { int v = spre[b]; spre[b] = run; run += v; }
    }
    __syncthreads();
    int i = blockIdx.x * blockDim.x + t;
    if (i < NN) {
        int tt = g_incl[i] + spre[i >> 10];
        g_ptr[i + 1] = tt;
        g_cur[i] = tt - g_cnt_in[i];
        if (i == 0) g_ptr[0] = 0;
    }
}

__global__ void fill_kernel(const int* __restrict__ ei,
                            const float* __restrict__ ew) {
    int e = blockIdx.x * blockDim.x + threadIdx.x;
    if (e < NE) {
        int r = ei[e];
        int c = ei[NE + e];
        int pos = atomicAdd(&g_cur[c], 1);
        g_csr_row[pos] = r;
        g_csr_norm[pos] = g_dinv[r] * ew[e] * g_dinv[c];
    }
}

// ================= W-resident pipelined FFMA2 GEMM -> bf16 table =================
// USE_ACT=0: X from fp32 Xext -> g_hb. USE_ACT=1: X from bf16 g_actb -> g_hb2.
#define WPAD 136
#define SM_W_FLOATS (128 * WPAD)
#define SM_X_FLOATS (2 * 16 * WPAD)
#define SM_GEMM_BYTES ((SM_W_FLOATS + SM_X_FLOATS) * 4)  // 87040

template <int USE_ACT>
__global__ void __launch_bounds__(256, 2)
gemm128_kernel(const float* __restrict__ Xext, const float* __restrict__ W,
               int row_start, int n) {
    extern __shared__ __align__(16) float sm[];
    float* Wsm = sm;                    // [128][WPAD]
    float* Xsm = sm + SM_W_FLOATS;      // [2][16][WPAD]

    uint32_t* __restrict__ Hout = USE_ACT ? g_hb2 : g_hb;

    int tid = threadIdx.x;
    int cx = tid & 15;
    int ry = tid >> 4;
    int row0 = row_start + blockIdx.x * 128;

    int lr   = tid >> 1;
    int half = tid & 1;
    int kb   = half * 8;

    int xrow = row0 + lr;
    bool ok = xrow < n;
    int srow = ok ? xrow : 0;
    const float*    Xp  = Xext + (size_t)srow * 128 + kb;
    const uint32_t* Xbp = g_actb + (size_t)srow * 64 + kb / 2;
    const float*    Wp  = W + lr * 128 + kb;

#pragma unroll
    for (int kc = 0; kc < 8; kc++) {
        float4 w0 = *reinterpret_cast<const float4*>(Wp + kc * 16);
        float4 w1 = *reinterpret_cast<const float4*>(Wp + kc * 16 + 4);
        float* dst = Wsm + (kc * 16 + kb) * WPAD + lr;
        dst[0 * WPAD] = w0.x; dst[1 * WPAD] = w0.y;
        dst[2 * WPAD] = w0.z; dst[3 * WPAD] = w0.w;
        dst[4 * WPAD] = w1.x; dst[5 * WPAD] = w1.y;
        dst[6 * WPAD] = w1.z; dst[7 * WPAD] = w1.w;
    }

    auto stage_x = [&](int b, const float4& a0, const float4& a1, const uint4& u) {
        float v[8];
        if (USE_ACT) {
            float2 f0 = bf2f(u.x), f1 = bf2f(u.y), f2 = bf2f(u.z), f3 = bf2f(u.w);
            v[0] = f0.x; v[1] = f0.y; v[2] = f1.x; v[3] = f1.y;
            v[4] = f2.x; v[5] = f2.y; v[6] = f3.x; v[7] = f3.y;
        } else {
            v[0] = a0.x; v[1] = a0.y; v[2] = a0.z; v[3] = a0.w;
            v[4] = a1.x; v[5] = a1.y; v[6] = a1.z; v[7] = a1.w;
        }
        float* dst = Xsm + (b * 16 + kb) * WPAD + lr;
#pragma unroll
        for (int j = 0; j < 8; j++) dst[j * WPAD] = ok ? v[j] : 0.f;
    };

    {
        float4 a0 = make_float4(0.f,0.f,0.f,0.f), a1 = a0;
        uint4 u = make_uint4(0,0,0,0);
        if (USE_ACT) u = *reinterpret_cast<const uint4*>(Xbp);
        else { a0 = *reinterpret_cast<const float4*>(Xp);
               a1 = *reinterpret_cast<const float4*>(Xp + 4); }
        stage_x(0, a0, a1, u);
    }
    __syncthreads();

    uint64_t acc[8][4];
#pragma unroll
    for (int a = 0; a < 8; a++)
#pragma unroll
        for (int b = 0; b < 4; b++) acc[a][b] = 0ull;

    float4 px0, px1; uint4 pu;
#pragma unroll
    for (int kc = 0; kc < 8; kc++) {
        int buf = kc & 1;
        if (kc < 7) {
            if (USE_ACT) pu = *reinterpret_cast<const uint4*>(Xbp + (kc + 1) * 8);
            else {
                px0 = *reinterpret_cast<const float4*>(Xp + (kc + 1) * 16);
                px1 = *reinterpret_cast<const float4*>(Xp + (kc + 1) * 16 + 4);
            }
        }

#pragma unroll
        for (int k = 0; k < 16; k++) {
            const float* wrow = Wsm + (kc * 16 + k) * WPAD;
            ulonglong2 wA = *reinterpret_cast<const ulonglong2*>(wrow + cx * 8);
            ulonglong2 wB = *reinterpret_cast<const ulonglong2*>(wrow + cx * 8 + 4);
            const float* xrowp = Xsm + (buf * 16 + k) * WPAD;
            float4 x0 = *reinterpret_cast<const float4*>(xrowp + ry * 8);
            float4 x1 = *reinterpret_cast<const float4*>(xrowp + ry * 8 + 4);
            float xr[8] = {x0.x, x0.y, x0.z, x0.w, x1.x, x1.y, x1.z, x1.w};
#pragma unroll
            for (int a = 0; a < 8; a++) {
                uint64_t xd;
                PACK2(xd, xr[a], xr[a]);
                FMA2(acc[a][0], xd, wA.x);
                FMA2(acc[a][1], xd, wA.y);
                FMA2(acc[a][2], xd, wB.x);
                FMA2(acc[a][3], xd, wB.y);
            }
        }
        if (kc < 7) {
            stage_x(buf ^ 1, px0, px1, pu);
            __syncthreads();
        }
    }

#pragma unroll
    for (int a = 0; a < 8; a++) {
        int r = row0 + ry * 8 + a;
        if (r < n) {
            uint4 o;
            float lo, hi;
            UNPACK2(lo, hi, acc[a][0]); CVT_BF2(o.x, lo, hi);
            UNPACK2(lo, hi, acc[a][1]); CVT_BF2(o.y, lo, hi);
            UNPACK2(lo, hi, acc[a][2]); CVT_BF2(o.z, lo, hi);
            UNPACK2(lo, hi, acc[a][3]); CVT_BF2(o.w, lo, hi);
            *reinterpret_cast<uint4*>(&Hout[(size_t)r * 64 + cx * 4]) = o;
        }
    }
}

// ================= fused aggregate + relu; act-store OR block-privatized pool =================
// SRC=0 reads g_hb (layer 1), SRC=1 reads g_hb2 (layer 2)
template <int SRC, int DO_POOL>
__global__ void gather_kernel(const float* __restrict__ bias,
                              const int* __restrict__ batch,
                              int node_start, int node_count) {
    __shared__ float sacc[8][128];
    __shared__ int sgid[8];

    int lw = (blockIdx.x * blockDim.x + threadIdx.x) >> 5;
    int lane = threadIdx.x & 31;
    int wid = threadIdx.x >> 5;
    bool valid = lw < node_count;
    int w = node_start + (valid ? lw : node_count - 1);

    const uint2* __restrict__ hb =
        reinterpret_cast<const uint2*>(SRC ? g_hb2 : g_hb);
    int start = g_ptr[w];
    int end   = g_ptr[w + 1];
    float di = g_dinv[w];
    float s = di * di;

    uint2 us = hb[(size_t)w * 32 + lane];
    float2 s0 = bf2f(us.x), s1 = bf2f(us.y);
    float4 bv = reinterpret_cast<const float4*>(bias)[lane];
    float4 acc;
    acc.x = s0.x * s + bv.x;
    acc.y = s0.y * s + bv.y;
    acc.z = s1.x * s + bv.z;
    acc.w = s1.y * s + bv.w;

    int e = start;
    for (; e + 8 <= end; e += 8) {
        int   ri[8];
        float ni[8];
#pragma unroll
        for (int j = 0; j < 8; j++) { ri[j] = g_csr_row[e + j]; ni[j] = g_csr_norm[e + j]; }
        uint2 v[8];
#pragma unroll
        for (int j = 0; j < 8; j++) v[j] = hb[(size_t)ri[j] * 32 + lane];
#pragma unroll
        for (int j = 0; j < 8; j++) {
            float2 p0 = bf2f(v[j].x), p1 = bf2f(v[j].y);
            acc.x += ni[j] * p0.x;
            acc.y += ni[j] * p0.y;
            acc.z += ni[j] * p1.x;
            acc.w += ni[j] * p1.y;
        }
    }
    if (e + 4 <= end) {
        int   r0 = g_csr_row[e],   r1 = g_csr_row[e+1];
        int   r2 = g_csr_row[e+2], r3 = g_csr_row[e+3];
        float n0 = g_csr_norm[e],   n1 = g_csr_norm[e+1];
        float n2 = g_csr_norm[e+2], n3 = g_csr_norm[e+3];
        uint2 v0 = hb[(size_t)r0 * 32 + lane];
        uint2 v1 = hb[(size_t)r1 * 32 + lane];
        uint2 v2 = hb[(size_t)r2 * 32 + lane];
        uint2 v3 = hb[(size_t)r3 * 32 + lane];
        float2 a0 = bf2f(v0.x), b0 = bf2f(v0.y);
        float2 a1 = bf2f(v1.x), b1 = bf2f(v1.y);
        float2 a2 = bf2f(v2.x), b2 = bf2f(v2.y);
        float2 a3 = bf2f(v3.x), b3 = bf2f(v3.y);
        acc.x += n0*a0.x + n1*a1.x + n2*a2.x + n3*a3.x;
        acc.y += n0*a0.y + n1*a1.y + n2*a2.y + n3*a3.y;
        acc.z += n0*b0.x + n1*b1.x + n2*b2.x + n3*b3.x;
        acc.w += n0*b0.y + n1*b1.y + n2*b2.y + n3*b3.y;
        e += 4;
    }
    for (; e < end; e++) {
        int   r0 = g_csr_row[e];
        float n0 = g_csr_norm[e];
        uint2 v0 = hb[(size_t)r0 * 32 + lane];
        float2 p0 = bf2f(v0.x), p1 = bf2f(v0.y);
        acc.x += n0*p0.x; acc.y += n0*p0.y;
        acc.z += n0*p1.x; acc.w += n0*p1.y;
    }

    acc.x = fmaxf(acc.x, 0.f); acc.y = fmaxf(acc.y, 0.f);
    acc.z = fmaxf(acc.z, 0.f); acc.w = fmaxf(acc.w, 0.f);

    if (!DO_POOL) {
        if (valid) {
            uint2 o;
            CVT_BF2(o.x, acc.x, acc.y);
            CVT_BF2(o.y, acc.z, acc.w);
            reinterpret_cast<uint2*>(g_actb)[(size_t)w * 32 + lane] = o;
        }
        return;
    }

    // block-privatized mean-pool accumulation (batch is sorted)
    int g = -1;
    if (valid) {
        g = batch[w];
        if (g < 0) g = 0;
        if (g >= NG) g = NG - 1;
    }
    if (lane == 0) sgid[wid] = g;
    *reinterpret_cast<float4*>(&sacc[wid][lane * 4]) = acc;
    __syncthreads();

    if (threadIdx.x < 128) {
        int f = threadIdx.x;
        float run = 0.f;
        int cur = sgid[0];
#pragma unroll
        for (int j = 0; j < 8; j++) {
            int gj = sgid[j];
            float v = sacc[j][f];
            if (gj != cur) {
                if (cur >= 0) atomicAdd(&g_pool[cur * F + f], run);
                run = 0.f;
                cur = gj;
            }
            run += v;
        }
        if (cur >= 0) atomicAdd(&g_pool[cur * F + f], run);
    }
}

// ================= head MLP =================
__global__ void head_kernel(const float* __restrict__ l1w, const float* __restrict__ l1b,
                            const float* __restrict__ l2w, const float* __restrict__ l2b,
                            float* __restrict__ out) {
    int g = blockIdx.x;
    int t = threadIdx.x;
    __shared__ float gv[F];
    __shared__ float hv[F];
    __shared__ float red[F];

    float c = fmaxf(g_cnt[g], 1.0f);
    gv[t] = g_pool[g * F + t] / c;
    __syncthreads();

    float s = l1b[t];
    const float* wrow = l1w + t * F;
#pragma unroll 8
    for (int k = 0; k < F; k++) s += wrow[k] * gv[k];
    hv[t] = fmaxf(s, 0.f);
    __syncthreads();

    for (int o = 0; o < 2; o++) {
        red[t] = l2w[o * F + t] * hv[t];
        __syncthreads();
        for (int st = 64; st > 0; st >>= 1) {
            if (t < st) red[t] += red[t + st];
            __syncthreads();
        }
        if (t == 0) out[g * 2 + o] = red[0] + l2b[o];
        __syncthreads();
    }
}

extern "C" void kernel_launch(void* const* d_in, const int* in_sizes, int n_in,
                              void* d_out, int out_size) {
    const float* x     = (const float*)d_in[0];
    const int*   ei    = (const int*)d_in[1];
    const float* ew    = (const float*)d_in[2];
    const int*   batch = (const int*)d_in[3];
    const float* W1    = (const float*)d_in[4];
    const float* b1    = (const float*)d_in[5];
    const float* W2    = (const float*)d_in[6];
    const float* b2    = (const float*)d_in[7];
    const float* l1w   = (const float*)d_in[8];
    const float* l1b   = (const float*)d_in[9];
    const float* l2w   = (const float*)d_in[10];
    const float* l2b   = (const float*)d_in[11];
    float* out         = (float*)d_out;

    // lazily-created side stream + events (host objects only; no device memory)
    static cudaStream_t s2 = nullptr;
    static cudaEvent_t ev_fork = nullptr, ev_gemm = nullptr, ev_g2done = nullptr;
    static cudaEvent_t ev_g1[NCHUNK];
    static int smem_set = 0;
    if (s2 == nullptr) {
        cudaStreamCreateWithFlags(&s2, cudaStreamNonBlocking);
        cudaEventCreateWithFlags(&ev_fork, cudaEventDisableTiming);
        cudaEventCreateWithFlags(&ev_gemm, cudaEventDisableTiming);
        cudaEventCreateWithFlags(&ev_g2done, cudaEventDisableTiming);
        for (int c = 0; c < NCHUNK; c++)
            cudaEventCreateWithFlags(&ev_g1[c], cudaEventDisableTiming);
    }
    if (!smem_set) {
        cudaFuncSetAttribute(gemm128_kernel<0>,
                             cudaFuncAttributeMaxDynamicSharedMemorySize, SM_GEMM_BYTES);
        cudaFuncSetAttribute(gemm128_kernel<1>,
                             cudaFuncAttributeMaxDynamicSharedMemorySize, SM_GEMM_BYTES);
        smem_set = 1;
    }

    const int T = 256;
    const int total_blocks = (NN + 127) / 128;          // 391
    int gather_blocks_full = (NN * 32 + T - 1) / T;

    int cb[NCHUNK + 1];
    for (int c = 0; c <= NCHUNK; c++) cb[c] = (total_blocks * c) / NCHUNK;

    // fork point: side stream joins the capture graph here
    cudaEventRecord(ev_fork, 0);
    cudaStreamWaitEvent(s2, ev_fork, 0);

    // branch A (main): CSR build; launches 1..3
    zero_misc_kernel<<<(NN + T - 1) / T, T>>>();
    deg_count_kernel<<<(NE / 4 + T - 1) / T, T>>>(ei, ew);
    scan1_kernel<<<NSB, SCAN_B>>>(batch);   // scan + dinv + graph counts

    // branch B (s2): GEMM layer 1 -> g_hb (4th launch -> ncu window)
    gemm128_kernel<0><<<total_blocks, T, SM_GEMM_BYTES, s2>>>(x, W1, 0, NN);
    cudaEventRecord(ev_gemm, s2);

    // branch A continued: finalize ptr/cur + fill
    scan3_kernel<<<(NN + T - 1) / T, T>>>();
    fill_kernel<<<(NE + T - 1) / T, T>>>(ei, ew);

    // join: gather1 needs CSR (A) AND g_hb from gemm1 (B)
    cudaStreamWaitEvent(0, ev_gemm, 0);

    // ---- pipelined gather1 (main, g_hb -> g_actb) / gemm2 (s2, g_actb -> g_hb2) ----
    for (int c = 0; c < NCHUNK; c++) {
        int nstart = cb[c] * 128;
        int ncount = min(NN, cb[c + 1] * 128) - nstart;
        int gblocks = (ncount * 32 + T - 1) / T;
        gather_kernel<0, 0><<<gblocks, T>>>(b1, batch, nstart, ncount);
        cudaEventRecord(ev_g1[c], 0);
        cudaStreamWaitEvent(s2, ev_g1[c], 0);
        int mblocks = cb[c + 1] - cb[c];
        gemm128_kernel<1><<<mblocks, T, SM_GEMM_BYTES, s2>>>(x, W2, nstart, NN);
    }
    cudaEventRecord(ev_g2done, s2);
    cudaStreamWaitEvent(0, ev_g2done, 0);

    // layer 2 aggregate from g_hb2 (+ privatized mean-pool, no act store)
    gather_kernel<1, 1><<<gather_blocks_full, T>>>(b2, batch, 0, NN);

    // head
    head_kernel<<<NG, F>>>(l1w, l1b, l2w, l2b, out);
}